// round 6
// baseline (speedup 1.0000x reference)
#include <cuda_runtime.h>
#include <cstdint>

// ---------------------------------------------------------------------------
// W8A8B32O32 Linear: out[8192,4096] = x[8192,4096]i8 @ w[4096,4096]i8^T + bias
//
// R5 theory: harness canonicalizes dtypes; output is float32 (int32 writes
// reinterpreted as float are NaN for negatives -> rel_err=nan on 4 rounds).
// This round:
//   1) runtime input-encoding detection (float32 / int32 / packed int8)
//   2) convert kernel -> __device__ int8/int32 scratch
//   3) dp4a GEMM (asm-free), fused bias, FLOAT32 output
//   4) B-fragment SMEM access remapped to 2-way-optimal bank pattern
// ---------------------------------------------------------------------------
#define TOKENS 8192
#define NDIM   4096
#define KDIM   4096

#define BM 128
#define BN 128
#define BK 64                 // K bytes per chunk = 16 words
#define NCHUNK (KDIM / BK)    // 64
#define THREADS 256
#define SSTRIDE 20            // words per SMEM row (80 B): 2-way-optimal banks

// ---- device scratch (module-scope: allowed; no runtime allocation) ----
__device__ __align__(16) int8_t g_x8[(size_t)TOKENS * KDIM];  // 32 MB
__device__ __align__(16) int8_t g_w8[(size_t)NDIM * KDIM];    // 16 MB
__device__ int g_b32[NDIM];
__device__ int g_mode[4];     // [0]=x, [1]=w, [2]=bias: 0=int8, 1=int32, 2=float32

// ---------------------------------------------------------------------------
// 1) input-encoding detection
// ---------------------------------------------------------------------------
__device__ int classify16(const uint32_t* p) {
    int fc = 0, ic = 0;
    for (int i = 0; i < 16; i++) {
        uint32_t u = p[i];
        if (((u >> 23) & 0xFF) != 0xFF) {           // finite as float
            float f = __uint_as_float(u);
            if (f == rintf(f) && fabsf(f) <= 4096.0f) fc++;  // integer-valued float
        }
        int v = (int)u;
        if (v >= -4096 && v <= 4096) ic++;          // small sign-extended int32
    }
    if (fc >= 12) return 2;
    if (ic >= 12) return 1;
    return 0;                                       // packed int8 bytes
}

__global__ void detect_kernel(const uint32_t* x, const uint32_t* w, const uint32_t* b) {
    if (threadIdx.x == 0 && blockIdx.x == 0) {
        g_mode[0] = classify16(x);
        g_mode[1] = classify16(w);
        g_mode[2] = classify16(b);
    }
}

// ---------------------------------------------------------------------------
// 2) convert inputs -> int8 / int32 scratch (grid-stride)
// ---------------------------------------------------------------------------
__device__ __forceinline__ char4 conv4(const void* src, size_t i, int mode) {
    if (mode == 2) {
        float4 v = ((const float4*)src)[i];
        return make_char4((char)__float2int_rn(v.x), (char)__float2int_rn(v.y),
                          (char)__float2int_rn(v.z), (char)__float2int_rn(v.w));
    } else if (mode == 1) {
        int4 v = ((const int4*)src)[i];
        return make_char4((char)v.x, (char)v.y, (char)v.z, (char)v.w);
    }
    return ((const char4*)src)[i];
}

__global__ void convert_kernel(const void* xs, const void* ws, const void* bs) {
    const int xm = g_mode[0], wm = g_mode[1], bm = g_mode[2];
    const size_t nx4 = (size_t)TOKENS * KDIM / 4;
    const size_t nw4 = (size_t)NDIM * KDIM / 4;
    const size_t stride = (size_t)gridDim.x * blockDim.x;
    const size_t t0 = (size_t)blockIdx.x * blockDim.x + threadIdx.x;

    for (size_t i = t0; i < nx4; i += stride)
        ((char4*)g_x8)[i] = conv4(xs, i, xm);
    for (size_t i = t0; i < nw4; i += stride)
        ((char4*)g_w8)[i] = conv4(ws, i, wm);
    for (size_t i = t0; i < NDIM; i += stride) {
        if (bm == 2)      g_b32[i] = __float2int_rn(((const float*)bs)[i]);
        else              g_b32[i] = ((const int*)bs)[i];
    }
}

// ---------------------------------------------------------------------------
// 3) dp4a GEMM, 128x128x64 tiles, 16x16 threads, 8x8 outputs/thread.
//    Thread -> N map is INTERLEAVED (col = tx + 16*j): B-fragment int4 LDS
//    hits 8 disjoint 4-bank spans covering all 32 banks -> 2-way (optimal).
//    A-fragment loads are uniform per half-warp -> broadcast.
// ---------------------------------------------------------------------------
__global__ __launch_bounds__(THREADS, 2)
void w8a8_dp4a_kernel(float* __restrict__ out)
{
    __shared__ __align__(16) int sA[BM][SSTRIDE];
    __shared__ __align__(16) int sB[BN][SSTRIDE];

    const int tid = threadIdx.x;
    const int tx  = tid & 15;          // interleaved col group
    const int ty  = tid >> 4;          // 8-row slab

    const int m_base = blockIdx.y * BM;
    const int n_base = blockIdx.x * BN;

    const int st_row = tid >> 2;       // 0..63
    const int st_seg = tid & 3;        // 16B segment of the 64B K-slice

    const int8_t* a_g = g_x8 + (size_t)m_base * KDIM;
    const int8_t* b_g = g_w8 + (size_t)n_base * KDIM;

    int acc[8][8];
    #pragma unroll
    for (int i = 0; i < 8; i++)
        #pragma unroll
        for (int j = 0; j < 8; j++)
            acc[i][j] = 0;

    for (int kc = 0; kc < NCHUNK; kc++) {
        const size_t gofs = (size_t)kc * BK + st_seg * 16;

        int4 va0 = *(const int4*)(a_g + (size_t)st_row * KDIM + gofs);
        int4 va1 = *(const int4*)(a_g + (size_t)(st_row + 64) * KDIM + gofs);
        int4 vb0 = *(const int4*)(b_g + (size_t)st_row * KDIM + gofs);
        int4 vb1 = *(const int4*)(b_g + (size_t)(st_row + 64) * KDIM + gofs);
        *(int4*)&sA[st_row][st_seg * 4]      = va0;
        *(int4*)&sA[st_row + 64][st_seg * 4] = va1;
        *(int4*)&sB[st_row][st_seg * 4]      = vb0;
        *(int4*)&sB[st_row + 64][st_seg * 4] = vb1;
        __syncthreads();

        #pragma unroll
        for (int kq = 0; kq < 4; kq++) {
            int4 bv[8];
            #pragma unroll
            for (int j = 0; j < 8; j++)
                bv[j] = *(const int4*)&sB[tx + 16 * j][kq * 4];

            #pragma unroll
            for (int i = 0; i < 8; i++) {
                int4 av = *(const int4*)&sA[ty * 8 + i][kq * 4];
                #pragma unroll
                for (int j = 0; j < 8; j++) {
                    int s = acc[i][j];
                    s = __dp4a(av.x, bv[j].x, s);
                    s = __dp4a(av.y, bv[j].y, s);
                    s = __dp4a(av.z, bv[j].z, s);
                    s = __dp4a(av.w, bv[j].w, s);
                    acc[i][j] = s;
                }
            }
        }
        __syncthreads();
    }

    // ---- epilogue: fused bias, FLOAT32 output ----
    int bcol[8];
    #pragma unroll
    for (int j = 0; j < 8; j++)
        bcol[j] = g_b32[n_base + tx + 16 * j];

    #pragma unroll
    for (int i = 0; i < 8; i++) {
        float* orow = out + (size_t)(m_base + ty * 8 + i) * NDIM + n_base;
        #pragma unroll
        for (int j = 0; j < 8; j++)
            orow[tx + 16 * j] = (float)(acc[i][j] + bcol[j]);
    }
}

// ---------------------------------------------------------------------------
// Launch wrapper: bind inputs by RELATIVE size (x > weight > bias holds under
// any dtype/units convention). Three sequential launches, graph-capturable.
// ---------------------------------------------------------------------------
extern "C" void kernel_launch(void* const* d_in, const int* in_sizes, int n_in,
                              void* d_out, int out_size)
{
    int ix = 0, iw = 1, ib = 2;
    if (n_in >= 3) {
        ix = 0; iw = 1; ib = 2;
        // order by size descending: largest=x, middle=weight, smallest=bias
        int idx[3] = {0, 1, 2};
        for (int a = 0; a < 3; a++)
            for (int b2 = a + 1; b2 < 3; b2++)
                if ((long)in_sizes[idx[b2]] > (long)in_sizes[idx[a]]) {
                    int t = idx[a]; idx[a] = idx[b2]; idx[b2] = t;
                }
        ix = idx[0]; iw = idx[1]; ib = idx[2];
    }

    const void* x  = d_in[ix];
    const void* w  = d_in[iw];
    const void* b  = d_in[ib];
    float* out = (float*)d_out;
    (void)out_size;

    detect_kernel<<<1, 32>>>((const uint32_t*)x, (const uint32_t*)w,
                             (const uint32_t*)b);
    convert_kernel<<<1024, 256>>>(x, w, b);

    dim3 grid(NDIM / BN, TOKENS / BM);   // (32, 64) = 2048 CTAs
    w8a8_dp4a_kernel<<<grid, THREADS>>>(out);
}

// round 7
// speedup vs baseline: 1.1123x; 1.1123x over previous
#include <cuda_runtime.h>
#include <cstdint>

// ---------------------------------------------------------------------------
// W8A8B32O32 Linear: out[8192,4096] = x[8192,4096]i8 @ w[4096,4096]i8^T + bias
//
// R6 (passing, 2176us, dp4a) -> R7: tensor-core IMMA mainloop.
//   - proven I/O scaffolding kept: detect dtype -> convert to int8 scratch,
//     FLOAT32 output epilogue (harness buffer is f32; int writes = NaN).
//   - mma.sync.aligned.m16n8k32.row.col.s32.s8.s8.s32 (sm_80+, base target)
//   - cp.async.cg double-buffered 128x128x64 tiles, 8 warps (64x32 warp tile)
// ---------------------------------------------------------------------------
#define TOKENS 8192
#define NDIM   4096
#define KDIM   4096

#define BM 128
#define BN 128
#define BK 64
#define NCHUNK (KDIM / BK)        // 64
#define THREADS 256               // 8 warps: 2 (M) x 4 (N)
#define ASTRIDE 80                // SMEM row stride bytes (64 data + 16 pad)

// ---- device scratch (module-scope: allowed; no runtime allocation) ----
__device__ __align__(16) int8_t g_x8[(size_t)TOKENS * KDIM];  // 32 MB
__device__ __align__(16) int8_t g_w8[(size_t)NDIM * KDIM];    // 16 MB
__device__ int g_b32[NDIM];
__device__ int g_mode[4];

// ---------------------------------------------------------------------------
// 1) input-encoding detection (proven in R6)
// ---------------------------------------------------------------------------
__device__ int classify16(const uint32_t* p) {
    int fc = 0, ic = 0;
    for (int i = 0; i < 16; i++) {
        uint32_t u = p[i];
        if (((u >> 23) & 0xFF) != 0xFF) {
            float f = __uint_as_float(u);
            if (f == rintf(f) && fabsf(f) <= 4096.0f) fc++;
        }
        int v = (int)u;
        if (v >= -4096 && v <= 4096) ic++;
    }
    if (fc >= 12) return 2;
    if (ic >= 12) return 1;
    return 0;
}

__global__ void detect_kernel(const uint32_t* x, const uint32_t* w, const uint32_t* b) {
    if (threadIdx.x == 0 && blockIdx.x == 0) {
        g_mode[0] = classify16(x);
        g_mode[1] = classify16(w);
        g_mode[2] = classify16(b);
    }
}

// ---------------------------------------------------------------------------
// 2) convert inputs -> int8 / int32 scratch (grid-stride)
// ---------------------------------------------------------------------------
__device__ __forceinline__ char4 conv4(const void* src, size_t i, int mode) {
    if (mode == 2) {
        float4 v = ((const float4*)src)[i];
        return make_char4((char)__float2int_rn(v.x), (char)__float2int_rn(v.y),
                          (char)__float2int_rn(v.z), (char)__float2int_rn(v.w));
    } else if (mode == 1) {
        int4 v = ((const int4*)src)[i];
        return make_char4((char)v.x, (char)v.y, (char)v.z, (char)v.w);
    }
    return ((const char4*)src)[i];
}

__global__ void convert_kernel(const void* xs, const void* ws, const void* bs) {
    const int xm = g_mode[0], wm = g_mode[1], bm = g_mode[2];
    const size_t nx4 = (size_t)TOKENS * KDIM / 4;
    const size_t nw4 = (size_t)NDIM * KDIM / 4;
    const size_t stride = (size_t)gridDim.x * blockDim.x;
    const size_t t0 = (size_t)blockIdx.x * blockDim.x + threadIdx.x;

    for (size_t i = t0; i < nx4; i += stride)
        ((char4*)g_x8)[i] = conv4(xs, i, xm);
    for (size_t i = t0; i < nw4; i += stride)
        ((char4*)g_w8)[i] = conv4(ws, i, wm);
    for (size_t i = t0; i < NDIM; i += stride) {
        if (bm == 2) g_b32[i] = __float2int_rn(((const float*)bs)[i]);
        else         g_b32[i] = ((const int*)bs)[i];
    }
}

// ---------------------------------------------------------------------------
// 3) IMMA GEMM
// ---------------------------------------------------------------------------
__device__ __forceinline__ uint32_t smem_u32(const void* p) {
    uint32_t a;
    asm("{ .reg .u64 t; cvta.to.shared.u64 t, %1; cvt.u32.u64 %0, t; }"
        : "=r"(a) : "l"(p));
    return a;
}

__device__ __forceinline__ void cp16(uint32_t dst, const void* src) {
    asm volatile("cp.async.cg.shared.global [%0], [%1], 16;"
                 :: "r"(dst), "l"(src) : "memory");
}
#define CP_COMMIT() asm volatile("cp.async.commit_group;" ::: "memory")
#define CP_WAIT(n)  asm volatile("cp.async.wait_group %0;" :: "n"(n) : "memory")

__device__ __forceinline__ void mma_s8(int* c, const uint32_t* a, const uint32_t* b) {
    asm volatile(
        "mma.sync.aligned.m16n8k32.row.col.s32.s8.s8.s32 "
        "{%0,%1,%2,%3}, {%4,%5,%6,%7}, {%8,%9}, {%0,%1,%2,%3};"
        : "+r"(c[0]), "+r"(c[1]), "+r"(c[2]), "+r"(c[3])
        : "r"(a[0]), "r"(a[1]), "r"(a[2]), "r"(a[3]),
          "r"(b[0]), "r"(b[1]));
}

__global__ __launch_bounds__(THREADS, 2)
void w8a8_imma_kernel(float* __restrict__ out)
{
    __shared__ __align__(128) int8_t sA[2][BM * ASTRIDE];   // 2 x 10240 B
    __shared__ __align__(128) int8_t sB[2][BM * ASTRIDE];

    const int tid  = threadIdx.x;
    const int wid  = tid >> 5;
    const int lane = tid & 31;
    const int gid  = lane >> 2;     // 0..7
    const int tig  = lane & 3;      // 0..3

    const int warp_m = wid >> 2;    // 0..1  -> 64-row slab
    const int warp_n = wid & 3;     // 0..3  -> 32-col slab

    const int m_base = blockIdx.y * BM;
    const int n_base = blockIdx.x * BN;

    const int8_t* a_g = g_x8 + (size_t)m_base * KDIM;
    const int8_t* b_g = g_w8 + (size_t)n_base * KDIM;

    const int st_row = tid >> 2;    // 0..63
    const int st_seg = tid & 3;     // 16B segment of the 64B K-slice

    auto stage = [&](int kc, int buf) {
        const size_t gofs = (size_t)kc * BK + st_seg * 16;
        const uint32_t sofs = (uint32_t)(st_row * ASTRIDE + st_seg * 16);
        uint32_t a_s = smem_u32(&sA[buf][0]);
        uint32_t b_s = smem_u32(&sB[buf][0]);
        cp16(a_s + sofs,                a_g + (size_t)st_row * KDIM + gofs);
        cp16(a_s + sofs + 64 * ASTRIDE, a_g + (size_t)(st_row + 64) * KDIM + gofs);
        cp16(b_s + sofs,                b_g + (size_t)st_row * KDIM + gofs);
        cp16(b_s + sofs + 64 * ASTRIDE, b_g + (size_t)(st_row + 64) * KDIM + gofs);
    };

    int c[4][4][4];
    #pragma unroll
    for (int mf = 0; mf < 4; mf++)
        #pragma unroll
        for (int nf = 0; nf < 4; nf++)
            #pragma unroll
            for (int r = 0; r < 4; r++)
                c[mf][nf][r] = 0;

    stage(0, 0);
    CP_COMMIT();

    for (int kc = 0; kc < NCHUNK; kc++) {
        const int cur = kc & 1;

        if (kc + 1 < NCHUNK) {
            stage(kc + 1, cur ^ 1);
            CP_COMMIT();
            CP_WAIT(1);
        } else {
            CP_WAIT(0);
        }
        __syncthreads();

        const int8_t* Ab = &sA[cur][(warp_m * 64 + gid) * ASTRIDE];
        const int8_t* Bb = &sB[cur][(warp_n * 32 + gid) * ASTRIDE];

        #pragma unroll
        for (int ks = 0; ks < 2; ks++) {
            const int kofs = ks * 32 + tig * 4;

            // m16n8k32 s8 A fragment (k-stacked m16n8k16 pairs):
            //   a0=(row g, k-lo)  a1=(row g+8, k-lo)
            //   a2=(row g, k-hi)  a3=(row g+8, k-hi)
            uint32_t a[4][4];
            #pragma unroll
            for (int mf = 0; mf < 4; mf++) {
                const int8_t* ap = Ab + mf * 16 * ASTRIDE + kofs;
                a[mf][0] = *(const uint32_t*)(ap);
                a[mf][1] = *(const uint32_t*)(ap + 8 * ASTRIDE);
                a[mf][2] = *(const uint32_t*)(ap + 16);
                a[mf][3] = *(const uint32_t*)(ap + 8 * ASTRIDE + 16);
            }
            uint32_t b[4][2];
            #pragma unroll
            for (int nf = 0; nf < 4; nf++) {
                const int8_t* bp = Bb + nf * 8 * ASTRIDE + kofs;
                b[nf][0] = *(const uint32_t*)(bp);
                b[nf][1] = *(const uint32_t*)(bp + 16);
            }
            #pragma unroll
            for (int mf = 0; mf < 4; mf++)
                #pragma unroll
                for (int nf = 0; nf < 4; nf++)
                    mma_s8(c[mf][nf], a[mf], b[nf]);
        }
        __syncthreads();
    }

    // ---- epilogue: fused bias add, FLOAT32 output, float2 stores ----
    // C fragment: c0,c1 = (row g, cols 2tig, 2tig+1); c2,c3 = (row g+8, same)
    const int col0 = n_base + warp_n * 32 + tig * 2;

    int2 bv[4];
    #pragma unroll
    for (int nf = 0; nf < 4; nf++)
        bv[nf] = *(const int2*)(g_b32 + col0 + nf * 8);

    #pragma unroll
    for (int mf = 0; mf < 4; mf++) {
        const int row0 = m_base + warp_m * 64 + mf * 16 + gid;
        float* o0 = out + (size_t)row0 * NDIM;
        float* o1 = out + (size_t)(row0 + 8) * NDIM;
        #pragma unroll
        for (int nf = 0; nf < 4; nf++) {
            const int cc = col0 + nf * 8;
            float2 v0, v1;
            v0.x = (float)(c[mf][nf][0] + bv[nf].x);
            v0.y = (float)(c[mf][nf][1] + bv[nf].y);
            v1.x = (float)(c[mf][nf][2] + bv[nf].x);
            v1.y = (float)(c[mf][nf][3] + bv[nf].y);
            *(float2*)(o0 + cc) = v0;
            *(float2*)(o1 + cc) = v1;
        }
    }
}

// ---------------------------------------------------------------------------
// Launch wrapper: bind by relative size (x > weight > bias), 3 launches.
// ---------------------------------------------------------------------------
extern "C" void kernel_launch(void* const* d_in, const int* in_sizes, int n_in,
                              void* d_out, int out_size)
{
    int idx[3] = {0, 1, 2};
    if (n_in >= 3) {
        for (int a = 0; a < 3; a++)
            for (int b2 = a + 1; b2 < 3; b2++)
                if ((long)in_sizes[idx[b2]] > (long)in_sizes[idx[a]]) {
                    int t = idx[a]; idx[a] = idx[b2]; idx[b2] = t;
                }
    }
    const void* x = d_in[idx[0]];
    const void* w = d_in[idx[1]];
    const void* b = d_in[idx[2]];
    float* out = (float*)d_out;
    (void)out_size;

    detect_kernel<<<1, 32>>>((const uint32_t*)x, (const uint32_t*)w,
                             (const uint32_t*)b);
    convert_kernel<<<1024, 256>>>(x, w, b);

    dim3 grid(NDIM / BN, TOKENS / BM);   // (32, 64) = 2048 CTAs
    w8a8_imma_kernel<<<grid, THREADS>>>(out);
}

// round 9
// speedup vs baseline: 6.2279x; 5.5992x over previous
#include <cuda_runtime.h>
#include <cuda_bf16.h>
#include <cstdint>

// ---------------------------------------------------------------------------
// W8A8B32O32 Linear: out[8192,4096] = x[8192,4096]i8 @ w[4096,4096]i8^T + bias
//
// R9: sm_103a has NO integer tensor kind (kind::i8 rejected). Use tcgen05
// kind::f16 with bf16 operands (int8 exact in bf16; fp32 accum error ~1e-6
// rel << 1e-3 threshold).
//  - convert kernel: inputs -> bf16 scratch PRE-TILED + PRE-SW128-SWIZZLED
//  - GEMM: cp.async.bulk (2 instrs / 48KB chunk; avoids LSU issue wall),
//    warp-specialized producer/consumer, double-buffered mbarrier pipeline,
//    128x256 CTA tile, TMEM f32 accumulators, fused bias f32 epilogue.
// ---------------------------------------------------------------------------
#define TOKENS 8192
#define NDIM   4096
#define KDIM   4096

#define TM 128
#define TN 256
#define KC 64                     // K elems per chunk (128 B of bf16)
#define CHUNKS (KDIM / KC)        // 64
#define MT (TOKENS / TM)          // 64
#define NT (NDIM / TN)            // 16

#define A_TILE 16384              // 128 rows x 128 B
#define B_TILE 32768              // 256 rows x 128 B
#define STAGE_BYTES (A_TILE + B_TILE)          // 49152
#define TC_SMEM (2048 + 2 * STAGE_BYTES)       // header slack + 2 stages

// Feature gate: arch-specific ('a'/family) device pass only.
#if defined(__CUDA_ARCH_FEAT_SM103_ALL) || defined(__CUDA_ARCH_FEAT_SM100_ALL) || \
    defined(__CUDA_ARCH_SPECIFIC__) || defined(__CUDA_ARCH_FAMILY_SPECIFIC__)
#define W8A8_TC 1
#else
#define W8A8_TC 0
#endif

#define SW128(off) ((off) ^ (((off) >> 3) & 0x70))

// ---- device scratch: pre-tiled, pre-swizzled bf16 operands ----
// A: [mt(64)][kc(64)] tiles of 16KB ; B: [nt(16)][kc(64)] tiles of 32KB
__device__ __align__(1024) uint8_t g_xt[(size_t)MT * CHUNKS * A_TILE];  // 64 MB
__device__ __align__(1024) uint8_t g_wt[(size_t)NT * CHUNKS * B_TILE];  // 32 MB
__device__ float g_bf[NDIM];

// ---------------------------------------------------------------------------
// convert: classify dtype, write bf16 pre-tiled scratch
// ---------------------------------------------------------------------------
__device__ int classify16(const uint32_t* p) {
    int fc = 0, ic = 0;
    for (int i = 0; i < 16; i++) {
        uint32_t u = p[i];
        if (((u >> 23) & 0xFF) != 0xFF) {
            float f = __uint_as_float(u);
            if (f == rintf(f) && fabsf(f) <= 4096.0f) fc++;
        }
        int v = (int)u;
        if (v >= -4096 && v <= 4096) ic++;
    }
    if (fc >= 12) return 2;   // float32
    if (ic >= 12) return 1;   // int32
    return 0;                 // packed int8
}

__device__ __forceinline__ void load8f(const void* src, size_t e0, int mode, float* f) {
    if (mode == 0) {
        uint2 r = *(const uint2*)((const int8_t*)src + e0);
        f[0] = (float)(int)(signed char)(r.x);
        f[1] = (float)(int)(signed char)(r.x >> 8);
        f[2] = (float)(int)(signed char)(r.x >> 16);
        f[3] = (float)(int)(signed char)(r.x >> 24);
        f[4] = (float)(int)(signed char)(r.y);
        f[5] = (float)(int)(signed char)(r.y >> 8);
        f[6] = (float)(int)(signed char)(r.y >> 16);
        f[7] = (float)(int)(signed char)(r.y >> 24);
    } else if (mode == 1) {
        int4 a = ((const int4*)src)[e0 / 4];
        int4 b = ((const int4*)src)[e0 / 4 + 1];
        f[0] = (float)a.x; f[1] = (float)a.y; f[2] = (float)a.z; f[3] = (float)a.w;
        f[4] = (float)b.x; f[5] = (float)b.y; f[6] = (float)b.z; f[7] = (float)b.w;
    } else {
        float4 a = ((const float4*)src)[e0 / 4];
        float4 b = ((const float4*)src)[e0 / 4 + 1];
        f[0] = a.x; f[1] = a.y; f[2] = a.z; f[3] = a.w;
        f[4] = b.x; f[5] = b.y; f[6] = b.z; f[7] = b.w;
    }
}

__global__ void convert_kernel(const void* xs, const void* ws, const void* bs) {
    __shared__ int smode[3];
    if (threadIdx.x == 0) {
        smode[0] = classify16((const uint32_t*)xs);
        smode[1] = classify16((const uint32_t*)ws);
        smode[2] = classify16((const uint32_t*)bs);
    }
    __syncthreads();
    const int xm = smode[0], wm = smode[1], bm = smode[2];

    const size_t stride = (size_t)gridDim.x * blockDim.x;
    const size_t t0 = (size_t)blockIdx.x * blockDim.x + threadIdx.x;

    union { uint4 v; __nv_bfloat16 h[8]; } u;
    float f[8];

    // A: 64*64 tiles * 128 rows * 8 segs = 4,194,304 segs of 16B
    const size_t nsegA = (size_t)MT * CHUNKS * TM * 8;
    for (size_t i = t0; i < nsegA; i += stride) {
        const int seg = (int)(i & 7);
        const int row = (int)((i >> 3) & (TM - 1));
        const int t   = (int)(i >> 10);          // mt*64 + kc
        const int mt  = t >> 6, kc = t & 63;
        const size_t e0 = ((size_t)(mt * TM + row)) * KDIM + (size_t)kc * KC + seg * 8;
        load8f(xs, e0, xm, f);
        #pragma unroll
        for (int j = 0; j < 8; j++) u.h[j] = __float2bfloat16_rn(f[j]);
        *(uint4*)(g_xt + ((size_t)t << 14) + SW128((uint32_t)(row * 128 + seg * 16))) = u.v;
    }

    // B: 16*64 tiles * 256 rows * 8 segs = 2,097,152 segs
    const size_t nsegB = (size_t)NT * CHUNKS * TN * 8;
    for (size_t i = t0; i < nsegB; i += stride) {
        const int seg = (int)(i & 7);
        const int row = (int)((i >> 3) & (TN - 1));
        const int t   = (int)(i >> 11);          // nt*64 + kc
        const int nt  = t >> 6, kc = t & 63;
        const size_t e0 = ((size_t)(nt * TN + row)) * KDIM + (size_t)kc * KC + seg * 8;
        load8f(ws, e0, wm, f);
        #pragma unroll
        for (int j = 0; j < 8; j++) u.h[j] = __float2bfloat16_rn(f[j]);
        *(uint4*)(g_wt + ((size_t)t << 15) + SW128((uint32_t)(row * 128 + seg * 16))) = u.v;
    }

    for (size_t i = t0; i < NDIM; i += stride) {
        if (bm == 2) g_bf[i] = ((const float*)bs)[i];
        else         g_bf[i] = (float)((const int*)bs)[i];
    }
}

// ---------------------------------------------------------------------------
// tcgen05 machinery (arch-specific pass only)
// ---------------------------------------------------------------------------
__device__ __forceinline__ uint32_t smem_u32(const void* p) {
    uint32_t a;
    asm("{ .reg .u64 t; cvta.to.shared.u64 t, %1; cvt.u32.u64 %0, t; }"
        : "=r"(a) : "l"(p));
    return a;
}

#if W8A8_TC
// idesc kind::f16: dtype F32=1<<4, atype BF16=1<<7, btype BF16=1<<10,
// N/8<<17, M/16<<24  (validated against example 0x8080490 for M128/N32)
static constexpr uint32_t TC_IDESC =
    (1u << 4) | (1u << 7) | (1u << 10) | ((TN / 8) << 17) | ((TM / 16) << 24);

static constexpr uint64_t SMEM_DESC_BASE_SW128 =
    (uint64_t(2) << 61) | (uint64_t(1) << 46) | (uint64_t(64) << 32) | (uint64_t(1) << 16);
#define MAKE_SMEM_DESC(base_addr) \
    (SMEM_DESC_BASE_SW128 | ((uint64_t)((base_addr) >> 4) & 0x3FFF))

__device__ __forceinline__ void tc_mma_bf16(uint32_t d_tmem, uint64_t a_desc,
                                            uint64_t b_desc, uint32_t idesc, bool acc) {
    uint32_t en = acc ? 1u : 0u;
    asm volatile(
        "{ .reg .pred p; setp.ne.u32 p, %5, 0;\n\t"
        "tcgen05.mma.cta_group::1.kind::f16 [%0], %1, %2, %3, {%4, %4, %4, %4}, p; }"
        :: "r"(d_tmem), "l"(a_desc), "l"(b_desc), "r"(idesc), "r"(0u), "r"(en)
        : "memory");
}
__device__ __forceinline__ void bulk_g2s(uint32_t dst, const void* src,
                                         uint32_t bytes, uint32_t mbar) {
    asm volatile(
        "cp.async.bulk.shared::cta.global.mbarrier::complete_tx::bytes [%0], [%1], %2, [%3];"
        :: "r"(dst), "l"(src), "r"(bytes), "r"(mbar) : "memory");
}
#define TC_ALLOC(smem_addr, n) \
    asm volatile("tcgen05.alloc.cta_group::1.sync.aligned.shared::cta.b32 [%0], %1;" \
                 :: "r"((uint32_t)(smem_addr)), "r"((uint32_t)(n)) : "memory")
#define TC_DEALLOC(tmem, n) \
    asm volatile("tcgen05.dealloc.cta_group::1.sync.aligned.b32 %0, %1;" \
                 :: "r"(tmem), "r"((uint32_t)(n)))
#define TC_COMMIT(mbar) \
    asm volatile("tcgen05.commit.cta_group::1.mbarrier::arrive::one.shared::cluster.b64 [%0];" \
                 :: "r"((uint32_t)(mbar)) : "memory")
#define TC_FENCE_AFTER()  asm volatile("tcgen05.fence::after_thread_sync;" ::: "memory")
#define TC_FENCE_BEFORE() asm volatile("tcgen05.fence::before_thread_sync;" ::: "memory")
#define TC_WAIT_LD()      asm volatile("tcgen05.wait::ld.sync.aligned;" ::: "memory")
#define TC_LD_X32(r, addr) \
    asm volatile("tcgen05.ld.sync.aligned.32x32b.x32.b32 " \
        "{%0, %1, %2, %3, %4, %5, %6, %7, %8, %9, %10, %11, %12, %13, %14, %15, " \
        " %16, %17, %18, %19, %20, %21, %22, %23, %24, %25, %26, %27, %28, %29, %30, %31}, [%32];" \
        : "=r"((r)[0]), "=r"((r)[1]), "=r"((r)[2]), "=r"((r)[3]), \
          "=r"((r)[4]), "=r"((r)[5]), "=r"((r)[6]), "=r"((r)[7]), \
          "=r"((r)[8]), "=r"((r)[9]), "=r"((r)[10]), "=r"((r)[11]), \
          "=r"((r)[12]), "=r"((r)[13]), "=r"((r)[14]), "=r"((r)[15]), \
          "=r"((r)[16]), "=r"((r)[17]), "=r"((r)[18]), "=r"((r)[19]), \
          "=r"((r)[20]), "=r"((r)[21]), "=r"((r)[22]), "=r"((r)[23]), \
          "=r"((r)[24]), "=r"((r)[25]), "=r"((r)[26]), "=r"((r)[27]), \
          "=r"((r)[28]), "=r"((r)[29]), "=r"((r)[30]), "=r"((r)[31]) \
        : "r"(addr))
#define MBAR_INIT(mbar, n) \
    asm volatile("mbarrier.init.shared.b64 [%0], %1;" \
                 :: "r"((uint32_t)(mbar)), "r"((uint32_t)(n)) : "memory")
#define MBAR_EXPECT_TX(mbar, bytes) \
    asm volatile("mbarrier.arrive.expect_tx.shared.b64 _, [%0], %1;" \
                 :: "r"((uint32_t)(mbar)), "r"((uint32_t)(bytes)) : "memory")
#define MBAR_INVAL(mbar) \
    asm volatile("mbarrier.inval.shared.b64 [%0];" :: "r"((uint32_t)(mbar)) : "memory")
#define MBAR_WAIT(mbar, parity) do { \
    uint32_t _m = (uint32_t)(mbar), _p = (uint32_t)(parity), _d; \
    asm volatile("{ .reg .pred p; mbarrier.try_wait.parity.acquire.cta.shared::cta.b64 p, [%1], %2; selp.b32 %0, 1, 0, p; }" \
                 : "=r"(_d) : "r"(_m), "r"(_p) : "memory"); \
    if (!_d) { \
        asm volatile("{ .reg .pred P1;\n\tWL_%=:\n\t" \
            "mbarrier.try_wait.parity.acquire.cta.shared::cta.b64 P1, [%0], %1, 0x989680;\n\t" \
            "@P1 bra.uni WD_%=;\n\tbra.uni WL_%=;\n\tWD_%=:\n\t}" \
            :: "r"(_m), "r"(_p) : "memory"); \
    } \
} while (0)
#define FENCE_PROXY() asm volatile("fence.proxy.async.shared::cta;" ::: "memory")
#endif  // W8A8_TC

__global__ __launch_bounds__(256, 1)
void w8a8_tc_kernel(float* __restrict__ out)
{
#if W8A8_TC
    extern __shared__ char dsm[];
    const uint32_t raw  = smem_u32(dsm);
    const uint32_t hdr  = (raw + 1023u) & ~1023u;     // [hdr]=tmem ptr
    const uint32_t full0 = hdr + 16;                  // full[s] = +16+8s
    const uint32_t mma0  = hdr + 48;                  // mma[s]  = +48+8s
    const uint32_t fin   = hdr + 80;
    const uint32_t tiles = hdr + 1024;

    const int tid  = threadIdx.x;
    const int wid  = tid >> 5;
    const int lane = tid & 31;
    const int nt = blockIdx.x;     // 0..15
    const int mt = blockIdx.y;     // 0..63

    if (wid == 0) TC_ALLOC(hdr, 256);
    if (tid == 0) {
        MBAR_INIT(full0, 1);     MBAR_INIT(full0 + 8, 1);
        MBAR_INIT(mma0, 1);      MBAR_INIT(mma0 + 8, 1);
        MBAR_INIT(fin, 1);
    }
    __syncthreads();
    FENCE_PROXY();
    uint32_t tmem;
    asm volatile("ld.shared.b32 %0, [%1];" : "=r"(tmem) : "r"(hdr));

    const uint8_t* a_src = g_xt + ((size_t)(mt * CHUNKS) << 14);
    const uint8_t* b_src = g_wt + ((size_t)(nt * CHUNKS) << 15);

    if (tid == 0) {
        // ---- producer: fill stage 0,1 then steady-state ----
        #pragma unroll
        for (int s = 0; s < 2; s++) {
            MBAR_EXPECT_TX(full0 + 8 * s, STAGE_BYTES);
            bulk_g2s(tiles + s * STAGE_BYTES,          a_src + ((size_t)s << 14), A_TILE, full0 + 8 * s);
            bulk_g2s(tiles + s * STAGE_BYTES + A_TILE, b_src + ((size_t)s << 15), B_TILE, full0 + 8 * s);
        }
        for (int kc = 2; kc < CHUNKS; kc++) {
            const int s = kc & 1;
            MBAR_WAIT(mma0 + 8 * s, ((kc >> 1) - 1) & 1);   // chunk kc-2 MMA done
            MBAR_EXPECT_TX(full0 + 8 * s, STAGE_BYTES);
            bulk_g2s(tiles + s * STAGE_BYTES,          a_src + ((size_t)kc << 14), A_TILE, full0 + 8 * s);
            bulk_g2s(tiles + s * STAGE_BYTES + A_TILE, b_src + ((size_t)kc << 15), B_TILE, full0 + 8 * s);
        }
    } else if (tid == 32) {
        // ---- consumer: MMA per chunk ----
        for (int kc = 0; kc < CHUNKS; kc++) {
            const int s = kc & 1;
            MBAR_WAIT(full0 + 8 * s, (kc >> 1) & 1);
            const uint64_t ad = MAKE_SMEM_DESC(tiles + s * STAGE_BYTES);
            const uint64_t bd = MAKE_SMEM_DESC(tiles + s * STAGE_BYTES + A_TILE);
            #pragma unroll
            for (int st = 0; st < 4; st++)   // K=16 per MMA, +32B = +2 desc units
                tc_mma_bf16(tmem, ad + st * 2, bd + st * 2, TC_IDESC, (kc > 0) || (st > 0));
            TC_COMMIT(mma0 + 8 * s);
        }
        TC_COMMIT(fin);   // completes when all prior MMAs retire
    }

    // ---- all threads: wait for final MMA, then epilogue ----
    MBAR_WAIT(fin, 0);
    TC_FENCE_AFTER();

    {
        const int sub  = wid & 3;              // TMEM subpartition = wid%4
        const int half = (wid >> 2) * 128;     // col half: 0 or 128
        const int row  = mt * TM + sub * 32 + lane;
        float* orow = out + (size_t)row * NDIM + nt * TN + half;
        const float* bb = g_bf + nt * TN + half;

        #pragma unroll
        for (int q = 0; q < 4; q++) {
            uint32_t d[32];
            TC_LD_X32(d, tmem + half + q * 32);
            TC_WAIT_LD();
            #pragma unroll
            for (int j = 0; j < 8; j++) {
                float4 bj = *(const float4*)(bb + q * 32 + j * 4);
                float4 v;
                v.x = __uint_as_float(d[j * 4 + 0]) + bj.x;
                v.y = __uint_as_float(d[j * 4 + 1]) + bj.y;
                v.z = __uint_as_float(d[j * 4 + 2]) + bj.z;
                v.w = __uint_as_float(d[j * 4 + 3]) + bj.w;
                *(float4*)(orow + q * 32 + j * 4) = v;
            }
        }
        TC_FENCE_BEFORE();
    }

    __syncthreads();
    if (tid == 0) {
        MBAR_INVAL(full0); MBAR_INVAL(full0 + 8);
        MBAR_INVAL(mma0);  MBAR_INVAL(mma0 + 8);
        MBAR_INVAL(fin);
    }
    __syncthreads();
    if (wid == 0) TC_DEALLOC(tmem, 256);
#endif  // W8A8_TC
}

// ---------------------------------------------------------------------------
// Launch wrapper: bind by relative size (x > weight > bias); 2 launches.
// ---------------------------------------------------------------------------
extern "C" void kernel_launch(void* const* d_in, const int* in_sizes, int n_in,
                              void* d_out, int out_size)
{
    int idx[3] = {0, 1, 2};
    if (n_in >= 3) {
        for (int a = 0; a < 3; a++)
            for (int b2 = a + 1; b2 < 3; b2++)
                if ((long)in_sizes[idx[b2]] > (long)in_sizes[idx[a]]) {
                    int t = idx[a]; idx[a] = idx[b2]; idx[b2] = t;
                }
    }
    const void* x = d_in[idx[0]];
    const void* w = d_in[idx[1]];
    const void* b = d_in[idx[2]];
    float* out = (float*)d_out;
    (void)out_size;

    cudaFuncSetAttribute(w8a8_tc_kernel,
                         cudaFuncAttributeMaxDynamicSharedMemorySize, TC_SMEM);

    convert_kernel<<<1024, 256>>>(x, w, b);

    dim3 grid(NT, MT);   // (16, 64) = 1024 CTAs
    w8a8_tc_kernel<<<grid, 256, TC_SMEM>>>(out);
}

// round 10
// speedup vs baseline: 8.5261x; 1.3690x over previous
#include <cuda_runtime.h>
#include <cuda_bf16.h>
#include <cstdint>

// ---------------------------------------------------------------------------
// W8A8B32O32 Linear: out[8192,4096] = x[8192,4096]i8 @ w[4096,4096]i8^T + bias
//
// R10: GEMM was LTS-cap bound (3.2GB L2 traffic @ ~6300 B/cyc = measured
// 302us). Reduce traffic 33% with 256x256 CTA tiles (TMEM 512 cols, two
// M=128 dispatches per k-step share one B read) + 3-stage bulk-copy pipeline.
// ---------------------------------------------------------------------------
#define TOKENS 8192
#define NDIM   4096
#define KDIM   4096

#define TM 256
#define TN 256
#define KC 64                     // K elems per chunk (128 B of bf16)
#define CHUNKS (KDIM / KC)        // 64
#define MT (TOKENS / TM)          // 32
#define NT (NDIM / TN)            // 16

#define A_TILE 32768              // 256 rows x 128 B
#define B_TILE 32768              // 256 rows x 128 B
#define STAGE_BYTES (A_TILE + B_TILE)          // 65536
#define NSTAGE 3
#define TC_SMEM (2048 + NSTAGE * STAGE_BYTES)  // 198656

// Feature gate: arch-specific ('a'/family) device pass only.
#if defined(__CUDA_ARCH_FEAT_SM103_ALL) || defined(__CUDA_ARCH_FEAT_SM100_ALL) || \
    defined(__CUDA_ARCH_SPECIFIC__) || defined(__CUDA_ARCH_FAMILY_SPECIFIC__)
#define W8A8_TC 1
#else
#define W8A8_TC 0
#endif

#define SW128(off) ((off) ^ (((off) >> 3) & 0x70))

// ---- device scratch: pre-tiled, pre-swizzled bf16 operands ----
// A: [mt(32)][kc(64)] tiles of 32KB ; B: [nt(16)][kc(64)] tiles of 32KB
__device__ __align__(1024) uint8_t g_xt[(size_t)MT * CHUNKS * A_TILE];  // 64 MB
__device__ __align__(1024) uint8_t g_wt[(size_t)NT * CHUNKS * B_TILE];  // 32 MB
__device__ float g_bf[NDIM];

// ---------------------------------------------------------------------------
// convert: classify dtype, write bf16 pre-tiled scratch
// ---------------------------------------------------------------------------
__device__ int classify16(const uint32_t* p) {
    int fc = 0, ic = 0;
    for (int i = 0; i < 16; i++) {
        uint32_t u = p[i];
        if (((u >> 23) & 0xFF) != 0xFF) {
            float f = __uint_as_float(u);
            if (f == rintf(f) && fabsf(f) <= 4096.0f) fc++;
        }
        int v = (int)u;
        if (v >= -4096 && v <= 4096) ic++;
    }
    if (fc >= 12) return 2;   // float32
    if (ic >= 12) return 1;   // int32
    return 0;                 // packed int8
}

__device__ __forceinline__ void load8f(const void* src, size_t e0, int mode, float* f) {
    if (mode == 0) {
        uint2 r = *(const uint2*)((const int8_t*)src + e0);
        f[0] = (float)(int)(signed char)(r.x);
        f[1] = (float)(int)(signed char)(r.x >> 8);
        f[2] = (float)(int)(signed char)(r.x >> 16);
        f[3] = (float)(int)(signed char)(r.x >> 24);
        f[4] = (float)(int)(signed char)(r.y);
        f[5] = (float)(int)(signed char)(r.y >> 8);
        f[6] = (float)(int)(signed char)(r.y >> 16);
        f[7] = (float)(int)(signed char)(r.y >> 24);
    } else if (mode == 1) {
        int4 a = ((const int4*)src)[e0 / 4];
        int4 b = ((const int4*)src)[e0 / 4 + 1];
        f[0] = (float)a.x; f[1] = (float)a.y; f[2] = (float)a.z; f[3] = (float)a.w;
        f[4] = (float)b.x; f[5] = (float)b.y; f[6] = (float)b.z; f[7] = (float)b.w;
    } else {
        float4 a = ((const float4*)src)[e0 / 4];
        float4 b = ((const float4*)src)[e0 / 4 + 1];
        f[0] = a.x; f[1] = a.y; f[2] = a.z; f[3] = a.w;
        f[4] = b.x; f[5] = b.y; f[6] = b.z; f[7] = b.w;
    }
}

__global__ void convert_kernel(const void* xs, const void* ws, const void* bs) {
    __shared__ int smode[3];
    if (threadIdx.x == 0) {
        smode[0] = classify16((const uint32_t*)xs);
        smode[1] = classify16((const uint32_t*)ws);
        smode[2] = classify16((const uint32_t*)bs);
    }
    __syncthreads();
    const int xm = smode[0], wm = smode[1], bm = smode[2];

    const size_t stride = (size_t)gridDim.x * blockDim.x;
    const size_t t0 = (size_t)blockIdx.x * blockDim.x + threadIdx.x;

    union { uint4 v; __nv_bfloat16 h[8]; } u;
    float f[8];

    // A: 32*64 tiles * 256 rows * 8 segs of 16B
    const size_t nsegA = (size_t)MT * CHUNKS * TM * 8;
    for (size_t i = t0; i < nsegA; i += stride) {
        const int seg = (int)(i & 7);
        const int row = (int)((i >> 3) & (TM - 1));
        const int t   = (int)(i >> 11);          // mt*64 + kc
        const int mt  = t >> 6, kc = t & 63;
        const size_t e0 = ((size_t)(mt * TM + row)) * KDIM + (size_t)kc * KC + seg * 8;
        load8f(xs, e0, xm, f);
        #pragma unroll
        for (int j = 0; j < 8; j++) u.h[j] = __float2bfloat16_rn(f[j]);
        *(uint4*)(g_xt + ((size_t)t << 15) + SW128((uint32_t)(row * 128 + seg * 16))) = u.v;
    }

    // B: 16*64 tiles * 256 rows * 8 segs
    const size_t nsegB = (size_t)NT * CHUNKS * TN * 8;
    for (size_t i = t0; i < nsegB; i += stride) {
        const int seg = (int)(i & 7);
        const int row = (int)((i >> 3) & (TN - 1));
        const int t   = (int)(i >> 11);          // nt*64 + kc
        const int nt  = t >> 6, kc = t & 63;
        const size_t e0 = ((size_t)(nt * TN + row)) * KDIM + (size_t)kc * KC + seg * 8;
        load8f(ws, e0, wm, f);
        #pragma unroll
        for (int j = 0; j < 8; j++) u.h[j] = __float2bfloat16_rn(f[j]);
        *(uint4*)(g_wt + ((size_t)t << 15) + SW128((uint32_t)(row * 128 + seg * 16))) = u.v;
    }

    for (size_t i = t0; i < NDIM; i += stride) {
        if (bm == 2) g_bf[i] = ((const float*)bs)[i];
        else         g_bf[i] = (float)((const int*)bs)[i];
    }
}

// ---------------------------------------------------------------------------
// tcgen05 machinery (arch-specific pass only)
// ---------------------------------------------------------------------------
__device__ __forceinline__ uint32_t smem_u32(const void* p) {
    uint32_t a;
    asm("{ .reg .u64 t; cvta.to.shared.u64 t, %1; cvt.u32.u64 %0, t; }"
        : "=r"(a) : "l"(p));
    return a;
}

#if W8A8_TC
// idesc kind::f16: dtype F32=1<<4, atype BF16=1<<7, btype BF16=1<<10,
// N/8<<17, M/16<<24  (M per dispatch = 128)
static constexpr uint32_t TC_IDESC =
    (1u << 4) | (1u << 7) | (1u << 10) | ((TN / 8) << 17) | ((128u / 16) << 24);

static constexpr uint64_t SMEM_DESC_BASE_SW128 =
    (uint64_t(2) << 61) | (uint64_t(1) << 46) | (uint64_t(64) << 32) | (uint64_t(1) << 16);
#define MAKE_SMEM_DESC(base_addr) \
    (SMEM_DESC_BASE_SW128 | ((uint64_t)((base_addr) >> 4) & 0x3FFF))

__device__ __forceinline__ void tc_mma_bf16(uint32_t d_tmem, uint64_t a_desc,
                                            uint64_t b_desc, uint32_t idesc, bool acc) {
    uint32_t en = acc ? 1u : 0u;
    asm volatile(
        "{ .reg .pred p; setp.ne.u32 p, %5, 0;\n\t"
        "tcgen05.mma.cta_group::1.kind::f16 [%0], %1, %2, %3, {%4, %4, %4, %4}, p; }"
        :: "r"(d_tmem), "l"(a_desc), "l"(b_desc), "r"(idesc), "r"(0u), "r"(en)
        : "memory");
}
__device__ __forceinline__ void bulk_g2s(uint32_t dst, const void* src,
                                         uint32_t bytes, uint32_t mbar) {
    asm volatile(
        "cp.async.bulk.shared::cta.global.mbarrier::complete_tx::bytes [%0], [%1], %2, [%3];"
        :: "r"(dst), "l"(src), "r"(bytes), "r"(mbar) : "memory");
}
#define TC_ALLOC(smem_addr, n) \
    asm volatile("tcgen05.alloc.cta_group::1.sync.aligned.shared::cta.b32 [%0], %1;" \
                 :: "r"((uint32_t)(smem_addr)), "r"((uint32_t)(n)) : "memory")
#define TC_DEALLOC(tmem, n) \
    asm volatile("tcgen05.dealloc.cta_group::1.sync.aligned.b32 %0, %1;" \
                 :: "r"(tmem), "r"((uint32_t)(n)))
#define TC_COMMIT(mbar) \
    asm volatile("tcgen05.commit.cta_group::1.mbarrier::arrive::one.shared::cluster.b64 [%0];" \
                 :: "r"((uint32_t)(mbar)) : "memory")
#define TC_FENCE_AFTER()  asm volatile("tcgen05.fence::after_thread_sync;" ::: "memory")
#define TC_FENCE_BEFORE() asm volatile("tcgen05.fence::before_thread_sync;" ::: "memory")
#define TC_WAIT_LD()      asm volatile("tcgen05.wait::ld.sync.aligned;" ::: "memory")
#define TC_LD_X32(r, addr) \
    asm volatile("tcgen05.ld.sync.aligned.32x32b.x32.b32 " \
        "{%0, %1, %2, %3, %4, %5, %6, %7, %8, %9, %10, %11, %12, %13, %14, %15, " \
        " %16, %17, %18, %19, %20, %21, %22, %23, %24, %25, %26, %27, %28, %29, %30, %31}, [%32];" \
        : "=r"((r)[0]), "=r"((r)[1]), "=r"((r)[2]), "=r"((r)[3]), \
          "=r"((r)[4]), "=r"((r)[5]), "=r"((r)[6]), "=r"((r)[7]), \
          "=r"((r)[8]), "=r"((r)[9]), "=r"((r)[10]), "=r"((r)[11]), \
          "=r"((r)[12]), "=r"((r)[13]), "=r"((r)[14]), "=r"((r)[15]), \
          "=r"((r)[16]), "=r"((r)[17]), "=r"((r)[18]), "=r"((r)[19]), \
          "=r"((r)[20]), "=r"((r)[21]), "=r"((r)[22]), "=r"((r)[23]), \
          "=r"((r)[24]), "=r"((r)[25]), "=r"((r)[26]), "=r"((r)[27]), \
          "=r"((r)[28]), "=r"((r)[29]), "=r"((r)[30]), "=r"((r)[31]) \
        : "r"(addr))
#define MBAR_INIT(mbar, n) \
    asm volatile("mbarrier.init.shared.b64 [%0], %1;" \
                 :: "r"((uint32_t)(mbar)), "r"((uint32_t)(n)) : "memory")
#define MBAR_EXPECT_TX(mbar, bytes) \
    asm volatile("mbarrier.arrive.expect_tx.shared.b64 _, [%0], %1;" \
                 :: "r"((uint32_t)(mbar)), "r"((uint32_t)(bytes)) : "memory")
#define MBAR_INVAL(mbar) \
    asm volatile("mbarrier.inval.shared.b64 [%0];" :: "r"((uint32_t)(mbar)) : "memory")
#define MBAR_WAIT(mbar, parity) do { \
    uint32_t _m = (uint32_t)(mbar), _p = (uint32_t)(parity), _d; \
    asm volatile("{ .reg .pred p; mbarrier.try_wait.parity.acquire.cta.shared::cta.b64 p, [%1], %2; selp.b32 %0, 1, 0, p; }" \
                 : "=r"(_d) : "r"(_m), "r"(_p) : "memory"); \
    if (!_d) { \
        asm volatile("{ .reg .pred P1;\n\tWL_%=:\n\t" \
            "mbarrier.try_wait.parity.acquire.cta.shared::cta.b64 P1, [%0], %1, 0x989680;\n\t" \
            "@P1 bra.uni WD_%=;\n\tbra.uni WL_%=;\n\tWD_%=:\n\t}" \
            :: "r"(_m), "r"(_p) : "memory"); \
    } \
} while (0)
#define FENCE_PROXY() asm volatile("fence.proxy.async.shared::cta;" ::: "memory")
#endif  // W8A8_TC

__global__ __launch_bounds__(256, 1)
void w8a8_tc_kernel(float* __restrict__ out)
{
#if W8A8_TC
    extern __shared__ char dsm[];
    const uint32_t raw   = smem_u32(dsm);
    const uint32_t hdr   = (raw + 1023u) & ~1023u;   // [hdr]=tmem ptr
    const uint32_t full0 = hdr + 16;                 // full[s] = +16+8s  (3)
    const uint32_t free0 = hdr + 48;                 // free[s] = +48+8s  (3)
    const uint32_t fin   = hdr + 96;
    const uint32_t tiles = hdr + 1024;

    const int tid  = threadIdx.x;
    const int wid  = tid >> 5;
    const int lane = tid & 31;
    const int nt = blockIdx.x;     // 0..15
    const int mt = blockIdx.y;     // 0..31

    if (wid == 0) TC_ALLOC(hdr, 512);
    if (tid == 0) {
        #pragma unroll
        for (int s = 0; s < NSTAGE; s++) {
            MBAR_INIT(full0 + 8 * s, 1);
            MBAR_INIT(free0 + 8 * s, 1);
        }
        MBAR_INIT(fin, 1);
    }
    __syncthreads();
    FENCE_PROXY();
    uint32_t tmem;
    asm volatile("ld.shared.b32 %0, [%1];" : "=r"(tmem) : "r"(hdr));

    const uint8_t* a_src = g_xt + ((size_t)(mt * CHUNKS) << 15);
    const uint8_t* b_src = g_wt + ((size_t)(nt * CHUNKS) << 15);

    if (tid == 0) {
        // ---- producer ----
        for (int kc = 0; kc < CHUNKS; kc++) {
            const int s = kc % NSTAGE;
            const int i = kc / NSTAGE;
            if (kc >= NSTAGE) MBAR_WAIT(free0 + 8 * s, (i - 1) & 1);
            MBAR_EXPECT_TX(full0 + 8 * s, STAGE_BYTES);
            bulk_g2s(tiles + s * STAGE_BYTES,          a_src + ((size_t)kc << 15),
                     A_TILE, full0 + 8 * s);
            bulk_g2s(tiles + s * STAGE_BYTES + A_TILE, b_src + ((size_t)kc << 15),
                     B_TILE, full0 + 8 * s);
        }
    } else if (tid == 32) {
        // ---- consumer: two M=128 dispatches per k-step (D0, D1) ----
        for (int kc = 0; kc < CHUNKS; kc++) {
            const int s = kc % NSTAGE;
            const int i = kc / NSTAGE;
            MBAR_WAIT(full0 + 8 * s, i & 1);
            const uint64_t a0 = MAKE_SMEM_DESC(tiles + s * STAGE_BYTES);
            const uint64_t a1 = MAKE_SMEM_DESC(tiles + s * STAGE_BYTES + A_TILE / 2);
            const uint64_t bd = MAKE_SMEM_DESC(tiles + s * STAGE_BYTES + A_TILE);
            const bool accb = (kc > 0);
            #pragma unroll
            for (int st = 0; st < 4; st++) {   // K=16 per MMA, +32B = +2 desc units
                tc_mma_bf16(tmem,       a0 + st * 2, bd + st * 2, TC_IDESC, accb || (st > 0));
                tc_mma_bf16(tmem + 256, a1 + st * 2, bd + st * 2, TC_IDESC, accb || (st > 0));
            }
            TC_COMMIT(free0 + 8 * s);
        }
        TC_COMMIT(fin);   // completes when all prior MMAs retire
    }

    // ---- all threads: wait for final MMA, then epilogue ----
    MBAR_WAIT(fin, 0);
    TC_FENCE_AFTER();

    {
        const int sub  = wid & 3;              // TMEM subpartition
        const int half = wid >> 2;             // 0: M rows 0-127, 1: rows 128-255
        const int row  = mt * TM + half * 128 + sub * 32 + lane;
        float* orow = out + (size_t)row * NDIM + nt * TN;
        const float* bb = g_bf + nt * TN;
        const uint32_t tbase = tmem + half * 256;

        #pragma unroll
        for (int q = 0; q < 8; q++) {
            uint32_t d[32];
            TC_LD_X32(d, tbase + q * 32);
            TC_WAIT_LD();
            #pragma unroll
            for (int j = 0; j < 8; j++) {
                float4 bj = *(const float4*)(bb + q * 32 + j * 4);
                float4 v;
                v.x = __uint_as_float(d[j * 4 + 0]) + bj.x;
                v.y = __uint_as_float(d[j * 4 + 1]) + bj.y;
                v.z = __uint_as_float(d[j * 4 + 2]) + bj.z;
                v.w = __uint_as_float(d[j * 4 + 3]) + bj.w;
                *(float4*)(orow + q * 32 + j * 4) = v;
            }
        }
        TC_FENCE_BEFORE();
    }

    __syncthreads();
    if (tid == 0) {
        #pragma unroll
        for (int s = 0; s < NSTAGE; s++) {
            MBAR_INVAL(full0 + 8 * s);
            MBAR_INVAL(free0 + 8 * s);
        }
        MBAR_INVAL(fin);
    }
    __syncthreads();
    if (wid == 0) TC_DEALLOC(tmem, 512);
#endif  // W8A8_TC
}

// ---------------------------------------------------------------------------
// Launch wrapper: bind by relative size (x > weight > bias); 2 launches.
// ---------------------------------------------------------------------------
extern "C" void kernel_launch(void* const* d_in, const int* in_sizes, int n_in,
                              void* d_out, int out_size)
{
    int idx[3] = {0, 1, 2};
    if (n_in >= 3) {
        for (int a = 0; a < 3; a++)
            for (int b2 = a + 1; b2 < 3; b2++)
                if ((long)in_sizes[idx[b2]] > (long)in_sizes[idx[a]]) {
                    int t = idx[a]; idx[a] = idx[b2]; idx[b2] = t;
                }
    }
    const void* x = d_in[idx[0]];
    const void* w = d_in[idx[1]];
    const void* b = d_in[idx[2]];
    float* out = (float*)d_out;
    (void)out_size;

    cudaFuncSetAttribute(w8a8_tc_kernel,
                         cudaFuncAttributeMaxDynamicSharedMemorySize, TC_SMEM);

    convert_kernel<<<2048, 256>>>(x, w, b);

    dim3 grid(NT, MT);   // (16, 32) = 512 CTAs
    w8a8_tc_kernel<<<grid, 256, TC_SMEM>>>(out);
}